// round 1
// baseline (speedup 1.0000x reference)
#include <cuda_runtime.h>
#include <cuda_fp16.h>
#include <mma.h>

using namespace nvcuda;

// Problem shape (fixed by the reference):
//   x:[8,4096,1024] f32, theta:[8], w1:[4096,8], b1:[4096], w2:[1024,4096], b2:[1024]
//   out:[8,4096,1024] f32
#define M_TOK 32768   // B*S tokens
#define E_DIM 1024    // embed
#define F_DIM 4096    // ffn
#define NQ 8

// Scratch (static __device__ arrays: allocation-free per harness rules)
__device__ __half g_H[(size_t)M_TOK * F_DIM];     // 256 MiB fp16 intermediate
__device__ __half g_w2h[(size_t)E_DIM * F_DIM];   // 8 MiB fp16 weights

// ---------------------------------------------------------------------------
// Kernel 1: h[t,f] = relu( sum_i cos(x[t,i])*cos(theta[i]) * w1[f,i] + b1[f] )
// Block: 256 threads, handles 64 tokens x 256 f-columns.
// ---------------------------------------------------------------------------
__global__ __launch_bounds__(256) void compute_h_kernel(
    const float* __restrict__ x, const float* __restrict__ theta,
    const float* __restrict__ w1, const float* __restrict__ b1)
{
    __shared__ float sq[64 * NQ];
    const int tid = threadIdx.x;
    const int t0 = blockIdx.y * 64;
    const int f  = blockIdx.x * 256 + tid;

    // q for 64 tokens (512 values), 2 per thread
    for (int idx = tid; idx < 64 * NQ; idx += 256) {
        int t = idx >> 3, i = idx & 7;
        sq[idx] = cosf(x[(size_t)(t0 + t) * E_DIM + i]) * cosf(theta[i]);
    }

    float w[NQ];
#pragma unroll
    for (int i = 0; i < NQ; i++) w[i] = w1[f * NQ + i];
    const float bb = b1[f];
    __syncthreads();

    __half* dst = g_H + (size_t)t0 * F_DIM + f;
#pragma unroll 4
    for (int t = 0; t < 64; t++) {
        float acc = bb;
#pragma unroll
        for (int i = 0; i < NQ; i++) acc = fmaf(sq[t * NQ + i], w[i], acc);
        acc = fmaxf(acc, 0.0f);
        dst[(size_t)t * F_DIM] = __float2half(acc);
    }
}

// ---------------------------------------------------------------------------
// Kernel 2: w2 f32 -> f16
// ---------------------------------------------------------------------------
__global__ __launch_bounds__(256) void convert_w2_kernel(const float* __restrict__ w2)
{
    int i = blockIdx.x * 256 + threadIdx.x;   // over E*F/4 float4s
    float4 v = ((const float4*)w2)[i];
    __half2 h0 = __floats2half2_rn(v.x, v.y);
    __half2 h1 = __floats2half2_rn(v.z, v.w);
    ((__half2*)g_w2h)[2 * i]     = h0;
    ((__half2*)g_w2h)[2 * i + 1] = h1;
}

// ---------------------------------------------------------------------------
// Kernel 3: out[m,n] = sum_k H[m,k] * w2[n,k]   (bias added in kernel 4)
// wmma m16n16k16 fp16->fp32. Tile BM=128, BN=128, BK=32. 8 warps:
// warp grid 4(m) x 2(n), each warp owns 32x64 (2x4 fragments).
// ---------------------------------------------------------------------------
#define BM 128
#define BN 128
#define BK 32
#define LDA 40   // halves, +8 pad
#define LDB 40

__global__ __launch_bounds__(256) void gemm_kernel(float* __restrict__ out)
{
    __shared__ __half As[BM * LDA];
    __shared__ __half Bs[BN * LDB];

    const int tid = threadIdx.x;
    const int n0 = blockIdx.x * BN;   // x fastest -> same-m0 CTAs adjacent (L2 reuse of A)
    const int m0 = blockIdx.y * BM;
    const int warp = tid >> 5;
    const int wm = (warp >> 1) * 32;
    const int wn = (warp & 1) * 64;

    wmma::fragment<wmma::accumulator, 16, 16, 16, float> c[2][4];
#pragma unroll
    for (int i = 0; i < 2; i++)
#pragma unroll
        for (int j = 0; j < 4; j++) wmma::fill_fragment(c[i][j], 0.0f);

    for (int kt = 0; kt < F_DIM; kt += BK) {
        // Each tile = 128 rows x 32 halves = 512 uint4; 2 per thread per matrix.
#pragma unroll
        for (int r = 0; r < 2; r++) {
            int idx = tid + r * 256;
            int mm = idx >> 2, seg = idx & 3;
            *(uint4*)(As + mm * LDA + seg * 8) =
                *(const uint4*)(g_H + (size_t)(m0 + mm) * F_DIM + kt + seg * 8);
            *(uint4*)(Bs + mm * LDB + seg * 8) =
                *(const uint4*)(g_w2h + (size_t)(n0 + mm) * F_DIM + kt + seg * 8);
        }
        __syncthreads();

#pragma unroll
        for (int kk = 0; kk < BK; kk += 16) {
            wmma::fragment<wmma::matrix_a, 16, 16, 16, __half, wmma::row_major> a[2];
            wmma::fragment<wmma::matrix_b, 16, 16, 16, __half, wmma::col_major> b[4];
#pragma unroll
            for (int i = 0; i < 2; i++)
                wmma::load_matrix_sync(a[i], As + (wm + i * 16) * LDA + kk, LDA);
#pragma unroll
            for (int j = 0; j < 4; j++)
                wmma::load_matrix_sync(b[j], Bs + (wn + j * 16) * LDB + kk, LDB);
#pragma unroll
            for (int i = 0; i < 2; i++)
#pragma unroll
                for (int j = 0; j < 4; j++)
                    wmma::mma_sync(c[i][j], a[i], b[j], c[i][j]);
        }
        __syncthreads();
    }

#pragma unroll
    for (int i = 0; i < 2; i++)
#pragma unroll
        for (int j = 0; j < 4; j++)
            wmma::store_matrix_sync(
                out + (size_t)(m0 + wm + i * 16) * E_DIM + (n0 + wn + j * 16),
                c[i][j], E_DIM, wmma::mem_row_major);
}

// ---------------------------------------------------------------------------
// Kernel 4: out += b2 (broadcast over rows), float4 vectorized
// ---------------------------------------------------------------------------
__global__ __launch_bounds__(256) void bias_kernel(float* __restrict__ out,
                                                   const float* __restrict__ b2)
{
    size_t i = (size_t)blockIdx.x * 256 + threadIdx.x;  // over M*E/4
    float4 v = ((float4*)out)[i];
    float4 bv = ((const float4*)b2)[i & 255];           // 256 float4 per row of 1024
    v.x += bv.x; v.y += bv.y; v.z += bv.z; v.w += bv.w;
    ((float4*)out)[i] = v;
}

// ---------------------------------------------------------------------------
extern "C" void kernel_launch(void* const* d_in, const int* in_sizes, int n_in,
                              void* d_out, int out_size)
{
    const float* x     = (const float*)d_in[0];
    const float* theta = (const float*)d_in[1];
    const float* w1    = (const float*)d_in[2];
    const float* b1    = (const float*)d_in[3];
    const float* w2    = (const float*)d_in[4];
    const float* b2    = (const float*)d_in[5];
    float* out = (float*)d_out;

    dim3 gh(F_DIM / 256, M_TOK / 64);
    compute_h_kernel<<<gh, 256>>>(x, theta, w1, b1);

    convert_w2_kernel<<<(E_DIM * F_DIM / 4) / 256, 256>>>(w2);

    dim3 gg(E_DIM / BN, M_TOK / BM);
    gemm_kernel<<<gg, 256>>>(out);

    bias_kernel<<<(unsigned)((size_t)M_TOK * E_DIM / 4 / 256), 256>>>(out, b2);
}

// round 3
// speedup vs baseline: 5.2391x; 5.2391x over previous
#include <cuda_runtime.h>
#include <cuda_fp16.h>
#include <cstdint>

// Shapes: x:[8,4096,1024]f32, theta:[8], w1:[4096,8], b1:[4096], w2:[1024,4096], b2:[1024]
// out:[8,4096,1024] f32
#define M_TOK 32768
#define E_DIM 1024
#define F_DIM 4096
#define NQ 8

// Arch guard: tcgen05 is only legal on arch-specific targets (sm_103a / sm_100a).
// The harness also builds generic compute_103 PTX; give it a stub body there.
#if defined(__CUDA_ARCH_FEAT_SM103_ALL) || defined(__CUDA_ARCH_FEAT_SM100_ALL) || !defined(__CUDA_ARCH__)
#define HAS_TCGEN05 1
#else
#define HAS_TCGEN05 0
#endif

// Static device scratch (allocation-free per harness rules)
__device__ __half g_H[(size_t)M_TOK * F_DIM];     // 256 MiB fp16 intermediate
__device__ __half g_w2h[(size_t)E_DIM * F_DIM];   // 8 MiB fp16 weights

// ===========================================================================
// PTX helpers
// ===========================================================================
__device__ __forceinline__ uint32_t smem_u32(const void* p) {
    uint32_t a;
    asm("{ .reg .u64 t; cvta.to.shared.u64 t, %1; cvt.u32.u64 %0, t; }" : "=r"(a) : "l"(p));
    return a;
}

#if HAS_TCGEN05 && defined(__CUDA_ARCH__)
__device__ __forceinline__ uint32_t elect_one() {
    uint32_t pred;
    asm volatile("{\n\t.reg .pred p;\n\telect.sync _|p, 0xFFFFFFFF;\n\tselp.b32 %0, 1, 0, p;\n\t}" : "=r"(pred));
    return pred;
}
#endif

#define MBAR_INIT(addr, cnt) \
    asm volatile("mbarrier.init.shared.b64 [%0], %1;" :: "r"(addr), "r"(cnt) : "memory")

#define MBAR_WAIT(addr, parity) do { \
    uint32_t _mb = (addr); uint32_t _p = (parity); uint32_t _done; \
    asm volatile("{\n\t.reg .pred p;\n\t" \
        "mbarrier.try_wait.parity.acquire.cta.shared::cta.b64 p, [%1], %2;\n\t" \
        "selp.b32 %0, 1, 0, p;\n\t}" : "=r"(_done) : "r"(_mb), "r"(_p) : "memory"); \
    if (!_done) { \
        asm volatile("{\n\t.reg .pred P1;\n\t" \
            "WL_%=:\n\t" \
            "mbarrier.try_wait.parity.acquire.cta.shared::cta.b64 P1, [%0], %1, 0x989680;\n\t" \
            "@P1 bra.uni WD_%=;\n\t" \
            "bra.uni WL_%=;\n\t" \
            "WD_%=:\n\t}" :: "r"(_mb), "r"(_p) : "memory"); \
    } \
} while (0)

#define CP_ASYNC16(dst, src) \
    asm volatile("cp.async.cg.shared.global [%0], [%1], 16;" :: "r"(dst), "l"(src) : "memory")
#define CP_COMMIT() asm volatile("cp.async.commit_group;" ::: "memory")
#define CP_WAIT1()  asm volatile("cp.async.wait_group 1;" ::: "memory")

#define TCGEN05_LD_X32(r, addr) \
    asm volatile("tcgen05.ld.sync.aligned.32x32b.x32.b32 " \
        "{%0, %1, %2, %3, %4, %5, %6, %7, " \
        " %8, %9, %10, %11, %12, %13, %14, %15, " \
        " %16, %17, %18, %19, %20, %21, %22, %23, " \
        " %24, %25, %26, %27, %28, %29, %30, %31}, [%32];" \
        : "=r"((r)[0]),  "=r"((r)[1]),  "=r"((r)[2]),  "=r"((r)[3]), \
          "=r"((r)[4]),  "=r"((r)[5]),  "=r"((r)[6]),  "=r"((r)[7]), \
          "=r"((r)[8]),  "=r"((r)[9]),  "=r"((r)[10]), "=r"((r)[11]), \
          "=r"((r)[12]), "=r"((r)[13]), "=r"((r)[14]), "=r"((r)[15]), \
          "=r"((r)[16]), "=r"((r)[17]), "=r"((r)[18]), "=r"((r)[19]), \
          "=r"((r)[20]), "=r"((r)[21]), "=r"((r)[22]), "=r"((r)[23]), \
          "=r"((r)[24]), "=r"((r)[25]), "=r"((r)[26]), "=r"((r)[27]), \
          "=r"((r)[28]), "=r"((r)[29]), "=r"((r)[30]), "=r"((r)[31]) \
        : "r"(addr))

#if HAS_TCGEN05 && defined(__CUDA_ARCH__)
// SS-mode f16 MMA, cta_group::1 (A desc + B desc, fp32 accum in TMEM)
__device__ __forceinline__ void mma_f16_ss(uint32_t d_tmem, uint64_t a_desc, uint64_t b_desc,
                                           uint32_t idesc, uint32_t enable) {
    asm volatile(
        "{\n\t.reg .pred p;\n\t"
        "setp.ne.u32 p, %4, 0;\n\t"
        "tcgen05.mma.cta_group::1.kind::f16 [%0], %1, %2, %3, {%5, %5, %5, %5}, p;\n\t}"
        :: "r"(d_tmem), "l"(a_desc), "l"(b_desc), "r"(idesc), "r"(enable), "r"(0u)
        : "memory");
}
#endif

// SW128 K-major smem descriptor: layout=2, version=1(Blackwell), SBO=64, LBO=1
static constexpr uint64_t DESC_BASE_SW128 =
    (uint64_t(2) << 61) | (uint64_t(1) << 46) | (uint64_t(64) << 32) | (uint64_t(1) << 16);
__device__ __forceinline__ uint64_t make_desc(uint32_t addr) {
    return DESC_BASE_SW128 | (uint64_t)((addr >> 4) & 0x3FFF);
}

// ===========================================================================
// Kernel 1: h[t,f] = relu( sum_i cos(x[t,i])*cos(theta[i]) * w1[f,i] + b1[f] ) -> fp16
// ===========================================================================
__global__ __launch_bounds__(256) void compute_h_kernel(
    const float* __restrict__ x, const float* __restrict__ theta,
    const float* __restrict__ w1, const float* __restrict__ b1)
{
    __shared__ float sq[64 * NQ];
    const int tid = threadIdx.x;
    const int t0 = blockIdx.y * 64;
    const int f  = blockIdx.x * 256 + tid;

    for (int idx = tid; idx < 64 * NQ; idx += 256) {
        int t = idx >> 3, i = idx & 7;
        sq[idx] = cosf(x[(size_t)(t0 + t) * E_DIM + i]) * cosf(theta[i]);
    }

    float w[NQ];
#pragma unroll
    for (int i = 0; i < NQ; i++) w[i] = w1[f * NQ + i];
    const float bb = b1[f];
    __syncthreads();

    __half* dst = g_H + (size_t)t0 * F_DIM + f;
#pragma unroll 4
    for (int t = 0; t < 64; t++) {
        float acc = bb;
#pragma unroll
        for (int i = 0; i < NQ; i++) acc = fmaf(sq[t * NQ + i], w[i], acc);
        acc = fmaxf(acc, 0.0f);
        dst[(size_t)t * F_DIM] = __float2half(acc);
    }
}

// ===========================================================================
// Kernel 2: w2 f32 -> f16
// ===========================================================================
__global__ __launch_bounds__(256) void convert_w2_kernel(const float* __restrict__ w2)
{
    int i = blockIdx.x * 256 + threadIdx.x;
    float4 v = ((const float4*)w2)[i];
    ((__half2*)g_w2h)[2 * i]     = __floats2half2_rn(v.x, v.y);
    ((__half2*)g_w2h)[2 * i + 1] = __floats2half2_rn(v.z, v.w);
}

// ===========================================================================
// Kernel 3: tcgen05 GEMM. out[m,n] = sum_k H[m,k]*w2[n,k] + b2[n]
// BM=256 (2 x M=128 TMEM accumulators, 512 TMEM cols), BN=256,
// K-tile = 64 halves (128B SW128 rows), 3-stage cp.async pipeline.
// ===========================================================================
#define BM 256
#define BN 256
#define KC 64
#define NKT (F_DIM / KC)              // 64
#define SA_BYTES (BM * 128)           // 32768
#define SB_BYTES (BN * 128)           // 32768
#define STAGE_BYTES (SA_BYTES + SB_BYTES)
#define SMEM_DATA 1024
#define GEMM_SMEM (SMEM_DATA + 3 * STAGE_BYTES)   // 197632

#if HAS_TCGEN05 && defined(__CUDA_ARCH__)
__device__ __forceinline__ void fill_stage(uint32_t sa, uint32_t sb,
                                           const __half* gA, const __half* gB, int tid)
{
#pragma unroll
    for (int i = 0; i < 8; i++) {
        int idx = tid + i * 256;          // 0..2047
        int row = idx >> 3;               // 0..255
        int c   = idx & 7;                // 16B chunk in 128B row
        uint32_t soff = row * 128 + ((c ^ (row & 7)) << 4);   // SW128 swizzle
        CP_ASYNC16(sa + soff, gA + (size_t)row * F_DIM + c * 8);
        CP_ASYNC16(sb + soff, gB + (size_t)row * F_DIM + c * 8);
    }
}
#endif

__global__ __launch_bounds__(256, 1) __cluster_dims__(1, 1, 1)
void gemm_tc_kernel(float* __restrict__ out, const float* __restrict__ b2)
{
#if HAS_TCGEN05 && defined(__CUDA_ARCH__)
    extern __shared__ char smem[];
    const uint32_t sbase = smem_u32(smem);
    const int tid  = threadIdx.x;
    const int warp = tid >> 5;
    const int lane = tid & 31;
    const int n0 = blockIdx.x * BN;
    const int m0 = blockIdx.y * BM;

    // TMEM alloc (all 512 cols)
    if (warp == 0) {
        asm volatile("tcgen05.alloc.cta_group::1.sync.aligned.shared::cta.b32 [%0], %1;"
                     :: "r"(sbase), "r"(512u) : "memory");
    }
    __syncthreads();
    uint32_t tmem;
    asm volatile("ld.shared.b32 %0, [%1];" : "=r"(tmem) : "r"(sbase));
    if (warp == 0)
        asm volatile("tcgen05.relinquish_alloc_permit.cta_group::1.sync.aligned;");

    // Two round-robin mbarriers at sbase+8, sbase+16
    if (tid == 0) { MBAR_INIT(sbase + 8, 1); MBAR_INIT(sbase + 16, 1); }
    __syncthreads();

    const __half* gA0 = g_H   + (size_t)m0 * F_DIM;
    const __half* gB0 = g_w2h + (size_t)n0 * F_DIM;
    // idesc: dtype=F32(1<<4), atype=btype=F16(0), N=256 -> 32<<17, M=128 -> 8<<24
    const uint32_t idesc = (1u << 4) | ((BN / 8) << 17) | ((128 / 16) << 24);

    // Prologue: stages 0,1 <- K-tiles 0,1
    fill_stage(sbase + SMEM_DATA,               sbase + SMEM_DATA + SA_BYTES,
               gA0,      gB0,      tid);
    CP_COMMIT();
    fill_stage(sbase + SMEM_DATA + STAGE_BYTES, sbase + SMEM_DATA + STAGE_BYTES + SA_BYTES,
               gA0 + KC, gB0 + KC, tid);
    CP_COMMIT();

    for (int kt = 0; kt < NKT; kt++) {
        const int s = kt % 3;
        CP_WAIT1();            // tile kt landed (<=1 group outstanding)
        __syncthreads();       // writes visible to all

        if (warp == 0 && elect_one()) {
            asm volatile("fence.proxy.async.shared::cta;" ::: "memory");
            uint32_t sa = sbase + SMEM_DATA + s * STAGE_BYTES;
            uint32_t sb = sa + SA_BYTES;
            uint64_t bdesc = make_desc(sb);
#pragma unroll
            for (int d = 0; d < 2; d++) {
                uint64_t adesc = make_desc(sa + d * 128 * 128);
#pragma unroll
                for (int k4 = 0; k4 < 4; k4++) {
                    // K16 step: +32B = +2 desc units
                    mma_f16_ss(tmem + d * 256, adesc + k4 * 2, bdesc + k4 * 2,
                               idesc, (kt > 0 || k4 > 0) ? 1u : 0u);
                }
            }
            uint32_t mb = sbase + 8 + (kt & 1) * 8;
            asm volatile("tcgen05.commit.cta_group::1.mbarrier::arrive::one.shared::cluster.b64 [%0];"
                         :: "r"(mb) : "memory");
        }

        // mma(kt-1) must finish before its buffer (stage (kt+2)%3) is refilled
        if (kt >= 1) {
            int j = kt - 1;
            MBAR_WAIT(sbase + 8 + (j & 1) * 8, (j >> 1) & 1);
        }
        if (kt + 2 < NKT) {
            int s2 = (kt + 2) % 3;
            fill_stage(sbase + SMEM_DATA + s2 * STAGE_BYTES,
                       sbase + SMEM_DATA + s2 * STAGE_BYTES + SA_BYTES,
                       gA0 + (size_t)(kt + 2) * KC, gB0 + (size_t)(kt + 2) * KC, tid);
        }
        CP_COMMIT();           // keep group count uniform
    }

    // Final commit j=63 -> mbar[1], parity (63>>1)&1 = 1
    MBAR_WAIT(sbase + 16, 1);
    asm volatile("tcgen05.fence::after_thread_sync;" ::: "memory");

    // Epilogue: wg0 reads D0 (rows m0..m0+127), wg1 reads D1 (+128). Bias fused.
    {
        const int wg = warp >> 2;
        const uint32_t dbase = tmem + wg * 256;
        const size_t row = (size_t)(m0 + wg * 128 + (warp & 3) * 32 + lane);
        float4* dst = (float4*)(out + row * E_DIM + n0);
        const float* bp = b2 + n0;
#pragma unroll
        for (int c0 = 0; c0 < BN; c0 += 32) {
            uint32_t r[32];
            TCGEN05_LD_X32(r, dbase + c0);
            asm volatile("tcgen05.wait::ld.sync.aligned;" ::: "memory");
#pragma unroll
            for (int q = 0; q < 8; q++) {
                float4 v;
                v.x = __uint_as_float(r[4 * q + 0]) + __ldg(bp + c0 + 4 * q + 0);
                v.y = __uint_as_float(r[4 * q + 1]) + __ldg(bp + c0 + 4 * q + 1);
                v.z = __uint_as_float(r[4 * q + 2]) + __ldg(bp + c0 + 4 * q + 2);
                v.w = __uint_as_float(r[4 * q + 3]) + __ldg(bp + c0 + 4 * q + 3);
                dst[(c0 >> 2) + q] = v;
            }
        }
        asm volatile("tcgen05.fence::before_thread_sync;" ::: "memory");
    }

    __syncthreads();
    if (tid == 0) {
        asm volatile("mbarrier.inval.shared.b64 [%0];" :: "r"(sbase + 8)  : "memory");
        asm volatile("mbarrier.inval.shared.b64 [%0];" :: "r"(sbase + 16) : "memory");
    }
    __syncthreads();
    if (warp == 0) {
        asm volatile("tcgen05.dealloc.cta_group::1.sync.aligned.b32 %0, %1;" :: "r"(tmem), "r"(512u));
    }
#endif  // HAS_TCGEN05
}

// ===========================================================================
extern "C" void kernel_launch(void* const* d_in, const int* in_sizes, int n_in,
                              void* d_out, int out_size)
{
    const float* x     = (const float*)d_in[0];
    const float* theta = (const float*)d_in[1];
    const float* w1    = (const float*)d_in[2];
    const float* b1    = (const float*)d_in[3];
    const float* w2    = (const float*)d_in[4];
    const float* b2    = (const float*)d_in[5];
    float* out = (float*)d_out;

    dim3 gh(F_DIM / 256, M_TOK / 64);
    compute_h_kernel<<<gh, 256>>>(x, theta, w1, b1);

    convert_w2_kernel<<<(E_DIM * F_DIM / 4) / 256, 256>>>(w2);

    cudaFuncSetAttribute(gemm_tc_kernel, cudaFuncAttributeMaxDynamicSharedMemorySize, GEMM_SMEM);
    dim3 gg(E_DIM / BN, M_TOK / BM);
    gemm_tc_kernel<<<gg, 256, GEMM_SMEM>>>(out, b2);
}

// round 6
// speedup vs baseline: 5.3138x; 1.0142x over previous
#include <cuda_runtime.h>
#include <cuda_fp16.h>
#include <cstdint>

// Shapes: x:[8,4096,1024]f32, theta:[8], w1:[4096,8], b1:[4096], w2:[1024,4096], b2:[1024]
// out:[8,4096,1024] f32
#define M_TOK 32768
#define E_DIM 1024
#define F_DIM 4096
#define NQ 8

// Arch guard: tcgen05 / bulk-multicast / f32x2 only legal on sm_103a-style targets.
#if defined(__CUDA_ARCH_FEAT_SM103_ALL) || defined(__CUDA_ARCH_FEAT_SM100_ALL) || !defined(__CUDA_ARCH__)
#define HAS_BLACKWELL 1
#else
#define HAS_BLACKWELL 0
#endif

// Static device scratch. Both stored in TILED+SWIZZLED layout:
//   tile (blk256, kt) at byte offset ((blk*64 + kt) * 32768);
//   within tile: row r (0..255) * 128 + ((c ^ (r&7)) << 4) for 16B chunk c (0..7).
__device__ __half g_H[(size_t)M_TOK * F_DIM];     // 256 MiB
__device__ __half g_w2h[(size_t)E_DIM * F_DIM];   // 8 MiB

// ===========================================================================
// PTX helpers
// ===========================================================================
__device__ __forceinline__ uint32_t smem_u32(const void* p) {
    uint32_t a;
    asm("{ .reg .u64 t; cvta.to.shared.u64 t, %1; cvt.u32.u64 %0, t; }" : "=r"(a) : "l"(p));
    return a;
}

#define MBAR_INIT(addr, cnt) \
    asm volatile("mbarrier.init.shared.b64 [%0], %1;" :: "r"(addr), "r"(cnt) : "memory")

#define MBAR_WAIT(addr, parity) do { \
    uint32_t _mb = (addr); uint32_t _p = (parity); uint32_t _done; \
    asm volatile("{\n\t.reg .pred p;\n\t" \
        "mbarrier.try_wait.parity.acquire.cta.shared::cta.b64 p, [%1], %2;\n\t" \
        "selp.b32 %0, 1, 0, p;\n\t}" : "=r"(_done) : "r"(_mb), "r"(_p) : "memory"); \
    if (!_done) { \
        asm volatile("{\n\t.reg .pred P1;\n\t" \
            "WL_%=:\n\t" \
            "mbarrier.try_wait.parity.acquire.cta.shared::cta.b64 P1, [%0], %1, 0x989680;\n\t" \
            "@P1 bra.uni WD_%=;\n\t" \
            "bra.uni WL_%=;\n\t" \
            "WD_%=:\n\t}" :: "r"(_mb), "r"(_p) : "memory"); \
    } \
} while (0)

#define MBAR_EXPECT_TX(addr, bytes) \
    asm volatile("mbarrier.arrive.expect_tx.shared.b64 _, [%0], %1;" \
                 :: "r"(addr), "r"(bytes) : "memory")

#if HAS_BLACKWELL && defined(__CUDA_ARCH__)
__device__ __forceinline__ uint32_t elect_one() {
    uint32_t pred;
    asm volatile("{\n\t.reg .pred p;\n\telect.sync _|p, 0xFFFFFFFF;\n\tselp.b32 %0, 1, 0, p;\n\t}" : "=r"(pred));
    return pred;
}
__device__ __forceinline__ uint32_t ctarank() {
    uint32_t r;
    asm("mov.u32 %0, %%cluster_ctarank;" : "=r"(r));
    return r;
}

#define BULK_G2S(dst, src, bytes, mbar) \
    asm volatile("cp.async.bulk.shared::cluster.global.mbarrier::complete_tx::bytes [%0], [%1], %2, [%3];" \
        :: "r"(dst), "l"(src), "r"(bytes), "r"(mbar) : "memory")

#define BULK_G2S_MC(dst, src, bytes, mbar, mask) \
    asm volatile("cp.async.bulk.shared::cluster.global.mbarrier::complete_tx::bytes.multicast::cluster [%0], [%1], %2, [%3], %4;" \
        :: "r"(dst), "l"(src), "r"(bytes), "r"(mbar), "h"((unsigned short)(mask)) : "memory")

// SS-mode f16 MMA, cta_group::1 (A desc + B desc, fp32 accum in TMEM)
__device__ __forceinline__ void mma_f16_ss(uint32_t d_tmem, uint64_t a_desc, uint64_t b_desc,
                                           uint32_t idesc, uint32_t enable) {
    asm volatile(
        "{\n\t.reg .pred p;\n\t"
        "setp.ne.u32 p, %4, 0;\n\t"
        "tcgen05.mma.cta_group::1.kind::f16 [%0], %1, %2, %3, {%5, %5, %5, %5}, p;\n\t}"
        :: "r"(d_tmem), "l"(a_desc), "l"(b_desc), "r"(idesc), "r"(enable), "r"(0u)
        : "memory");
}

// Packed fp32x2 accumulating FMA (FFMA2): d = a*b + d
__device__ __forceinline__ void fma2(unsigned long long& d, unsigned long long a,
                                     unsigned long long b) {
    asm("fma.rn.f32x2 %0, %1, %2, %0;" : "+l"(d) : "l"(a), "l"(b));
}
__device__ __forceinline__ unsigned long long pack2(float lo, float hi) {
    unsigned long long o;
    asm("mov.b64 %0, {%1, %2};" : "=l"(o) : "f"(lo), "f"(hi));
    return o;
}
__device__ __forceinline__ void unpack2(float& lo, float& hi, unsigned long long v) {
    asm("mov.b64 {%0, %1}, %2;" : "=f"(lo), "=f"(hi) : "l"(v));
}
#endif

#define TCGEN05_LD_X32(r, addr) \
    asm volatile("tcgen05.ld.sync.aligned.32x32b.x32.b32 " \
        "{%0, %1, %2, %3, %4, %5, %6, %7, " \
        " %8, %9, %10, %11, %12, %13, %14, %15, " \
        " %16, %17, %18, %19, %20, %21, %22, %23, " \
        " %24, %25, %26, %27, %28, %29, %30, %31}, [%32];" \
        : "=r"((r)[0]),  "=r"((r)[1]),  "=r"((r)[2]),  "=r"((r)[3]), \
          "=r"((r)[4]),  "=r"((r)[5]),  "=r"((r)[6]),  "=r"((r)[7]), \
          "=r"((r)[8]),  "=r"((r)[9]),  "=r"((r)[10]), "=r"((r)[11]), \
          "=r"((r)[12]), "=r"((r)[13]), "=r"((r)[14]), "=r"((r)[15]), \
          "=r"((r)[16]), "=r"((r)[17]), "=r"((r)[18]), "=r"((r)[19]), \
          "=r"((r)[20]), "=r"((r)[21]), "=r"((r)[22]), "=r"((r)[23]), \
          "=r"((r)[24]), "=r"((r)[25]), "=r"((r)[26]), "=r"((r)[27]), \
          "=r"((r)[28]), "=r"((r)[29]), "=r"((r)[30]), "=r"((r)[31]) \
        : "r"(addr))

// SW128 K-major smem descriptor: layout=2, version=1(Blackwell), SBO=64, LBO=1
static constexpr uint64_t DESC_BASE_SW128 =
    (uint64_t(2) << 61) | (uint64_t(1) << 46) | (uint64_t(64) << 32) | (uint64_t(1) << 16);
__device__ __forceinline__ uint64_t make_desc(uint32_t addr) {
    return DESC_BASE_SW128 | (uint64_t)((addr >> 4) & 0x3FFF);
}

// ===========================================================================
// Kernel 1: H (tiled+swizzled fp16) = relu(q @ w1^T + b1), q = cos(x[:, :8])*cos(theta)
// Grid: x = 2 (256 chunks each of the 512 K-chunks), y = 512 (64 tokens each).
// Thread owns one (kt, c) chunk = 8 consecutive f, loops 64 tokens; w1*cos(theta)
// held in registers as f32x2 pairs; one 16B coalesced store per token.
// ===========================================================================
__global__ __launch_bounds__(256) void compute_h_kernel(
    const float* __restrict__ x, const float* __restrict__ theta,
    const float* __restrict__ w1, const float* __restrict__ b1)
{
    __shared__ float sq[64 * NQ];   // cos(x) for 64 tokens; cos(theta) folded into weights
    const int tid = threadIdx.x;
    const int ch  = blockIdx.x * 256 + tid;    // 0..511
    const int kt  = ch >> 3;                   // K-tile 0..63
    const int c   = ch & 7;                    // chunk in tile
    const int f0  = kt * 64 + c * 8;
    const int ty0 = blockIdx.y * 64;

    for (int idx = tid; idx < 64 * NQ; idx += 256) {
        int t = idx >> 3, i = idx & 7;
        sq[idx] = cosf(x[(size_t)(ty0 + t) * E_DIM + i]);
    }

    float ct[NQ];
#pragma unroll
    for (int i = 0; i < NQ; i++) ct[i] = cosf(theta[i]);

#if HAS_BLACKWELL && defined(__CUDA_ARCH__)
    // wp[i][j] = ( w1[f0+2j][i]*ct[i], w1[f0+2j+1][i]*ct[i] )
    unsigned long long wp[NQ][4];
#pragma unroll
    for (int j = 0; j < 4; j++) {
        const float* r0 = w1 + (size_t)(f0 + 2 * j) * NQ;
        const float* r1 = r0 + NQ;
        float4 a0 = *(const float4*)(r0);
        float4 a1 = *(const float4*)(r0 + 4);
        float4 c0 = *(const float4*)(r1);
        float4 c1 = *(const float4*)(r1 + 4);
        wp[0][j] = pack2(a0.x * ct[0], c0.x * ct[0]);
        wp[1][j] = pack2(a0.y * ct[1], c0.y * ct[1]);
        wp[2][j] = pack2(a0.z * ct[2], c0.z * ct[2]);
        wp[3][j] = pack2(a0.w * ct[3], c0.w * ct[3]);
        wp[4][j] = pack2(a1.x * ct[4], c1.x * ct[4]);
        wp[5][j] = pack2(a1.y * ct[5], c1.y * ct[5]);
        wp[6][j] = pack2(a1.z * ct[6], c1.z * ct[6]);
        wp[7][j] = pack2(a1.w * ct[7], c1.w * ct[7]);
    }
    unsigned long long bb[4];
#pragma unroll
    for (int j = 0; j < 4; j++) bb[j] = pack2(b1[f0 + 2 * j], b1[f0 + 2 * j + 1]);

    __syncthreads();

    for (int n = 0; n < 64; n++) {
        unsigned long long acc[4] = { bb[0], bb[1], bb[2], bb[3] };
#pragma unroll
        for (int i = 0; i < NQ; i++) {
            float qv = sq[n * NQ + i];
            unsigned long long q2 = pack2(qv, qv);
#pragma unroll
            for (int j = 0; j < 4; j++) fma2(acc[j], q2, wp[i][j]);
        }
        uint4 vals;
        uint32_t* vp = (uint32_t*)&vals;
#pragma unroll
        for (int j = 0; j < 4; j++) {
            float lo, hi;
            unpack2(lo, hi, acc[j]);
            __half2 h2 = __floats2half2_rn(fmaxf(lo, 0.f), fmaxf(hi, 0.f));
            vp[j] = *(uint32_t*)&h2;
        }
        size_t t = (size_t)(ty0 + n);
        size_t mb = t >> 8;
        uint32_t r = (uint32_t)(t & 255);
        size_t off = ((mb * 64 + kt) << 15) + (size_t)r * 128 + (uint32_t)((c ^ (r & 7)) << 4);
        *(uint4*)((char*)g_H + off) = vals;
    }
#else
    // Scalar fallback (generic-PTX target only; never selected on GB300)
    float w[NQ][NQ], bbs[NQ];
#pragma unroll
    for (int fp = 0; fp < NQ; fp++) {
#pragma unroll
        for (int i = 0; i < NQ; i++) w[fp][i] = w1[(size_t)(f0 + fp) * NQ + i] * ct[i];
        bbs[fp] = b1[f0 + fp];
    }
    __syncthreads();
    for (int n = 0; n < 64; n++) {
        __half hv[NQ];
#pragma unroll
        for (int fp = 0; fp < NQ; fp++) {
            float acc = bbs[fp];
#pragma unroll
            for (int i = 0; i < NQ; i++) acc = fmaf(sq[n * NQ + i], w[fp][i], acc);
            hv[fp] = __float2half(fmaxf(acc, 0.f));
        }
        size_t t = (size_t)(ty0 + n);
        size_t mb = t >> 8;
        uint32_t r = (uint32_t)(t & 255);
        size_t off = ((mb * 64 + kt) << 15) + (size_t)r * 128 + (uint32_t)((c ^ (r & 7)) << 4);
        *(uint4*)((char*)g_H + off) = *(uint4*)hv;
    }
#endif
}

// ===========================================================================
// Kernel 2: w2 f32 -> f16 in tiled+swizzled layout
// idx -> (nb, kt, r, c): c=idx&7, r=(idx>>3)&255, kt=(idx>>11)&63, nb=idx>>17
// ===========================================================================
__global__ __launch_bounds__(256) void convert_w2_kernel(const float* __restrict__ w2)
{
    int idx = blockIdx.x * 256 + threadIdx.x;      // over E*F/8 = 524288 chunks
    int c  = idx & 7;
    int r  = (idx >> 3) & 255;
    int kt = (idx >> 11) & 63;
    int nb = idx >> 17;

    const float* src = w2 + ((size_t)(nb * 256 + r)) * F_DIM + kt * 64 + c * 8;
    float4 v0 = *(const float4*)(src);
    float4 v1 = *(const float4*)(src + 4);
    __half2 h0 = __floats2half2_rn(v0.x, v0.y);
    __half2 h1 = __floats2half2_rn(v0.z, v0.w);
    __half2 h2 = __floats2half2_rn(v1.x, v1.y);
    __half2 h3 = __floats2half2_rn(v1.z, v1.w);
    uint4 out;
    out.x = *(uint32_t*)&h0; out.y = *(uint32_t*)&h1;
    out.z = *(uint32_t*)&h2; out.w = *(uint32_t*)&h3;

    size_t off = (((size_t)nb * 64 + kt) << 15) + (size_t)r * 128 + (uint32_t)((c ^ (r & 7)) << 4);
    *(uint4*)((char*)g_w2h + off) = out;
}

// ===========================================================================
// Kernel 3: tcgen05 GEMM, BM=256, BN=256, KC=64 halves; 3-stage ring of
// cp.async.bulk loads (A: 1x32KB plain, B: 2x16KB multicast across (1,2,1)
// cluster — pair shares n0). Bias fused in TMEM-read epilogue.
// ===========================================================================
#define BM 256
#define BN 256
#define KC 64
#define NKT (F_DIM / KC)              // 64
#define TILE_BYTES 32768
#define STAGE_BYTES (2 * TILE_BYTES)  // A + B
#define SMEM_DATA 1024
#define GEMM_SMEM (SMEM_DATA + 3 * STAGE_BYTES)   // 197632

__global__ __launch_bounds__(256, 1) __cluster_dims__(1, 2, 1)
void gemm_tc_kernel(float* __restrict__ out, const float* __restrict__ b2)
{
#if HAS_BLACKWELL && defined(__CUDA_ARCH__)
    extern __shared__ char smem[];
    const uint32_t sbase = smem_u32(smem);
    const int tid  = threadIdx.x;
    const int warp = tid >> 5;
    const int lane = tid & 31;
    const int nb = blockIdx.x;
    const int n0 = nb * BN;
    const int m0 = blockIdx.y * BM;
    const uint32_t rank = ctarank();   // 0/1 within the y-pair

    // mbar addresses: full[0..2] at +8,+16,+24; mma ring at +32,+40
    const uint32_t mb_full0 = sbase + 8;
    const uint32_t mb_mma0  = sbase + 32;

    if (warp == 0) {
        asm volatile("tcgen05.alloc.cta_group::1.sync.aligned.shared::cta.b32 [%0], %1;"
                     :: "r"(sbase), "r"(512u) : "memory");
    }
    __syncthreads();
    uint32_t tmem;
    asm volatile("ld.shared.b32 %0, [%1];" : "=r"(tmem) : "r"(sbase));
    if (warp == 0)
        asm volatile("tcgen05.relinquish_alloc_permit.cta_group::1.sync.aligned;");

    if (tid == 0) {
        MBAR_INIT(mb_full0,      1); MBAR_INIT(mb_full0 + 8,  1); MBAR_INIT(mb_full0 + 16, 1);
        MBAR_INIT(mb_mma0,       1); MBAR_INIT(mb_mma0 + 8,   1);
    }
    __syncthreads();
    // All cluster mbarriers must be live before any multicast targets them.
    asm volatile("barrier.cluster.arrive.aligned;" ::: "memory");
    asm volatile("barrier.cluster.wait.aligned;"   ::: "memory");

    const char* Abase = (const char*)g_H   + ((size_t)blockIdx.y * 64) * TILE_BYTES;
    const char* Bbase = (const char*)g_w2h + ((size_t)nb * 64) * TILE_BYTES;
    // idesc: dtype=F32(1<<4), N=256 -> 32<<17, M=128 -> 8<<24
    const uint32_t idesc = (1u << 4) | ((BN / 8) << 17) | ((128 / 16) << 24);

    // Prologue: issue tiles 0,1 into stages 0,1
    if (tid == 0) {
#pragma unroll
        for (int p = 0; p < 2; p++) {
            uint32_t mb = mb_full0 + p * 8;
            uint32_t sa = sbase + SMEM_DATA + p * STAGE_BYTES;
            uint32_t sb = sa + TILE_BYTES;
            MBAR_EXPECT_TX(mb, (uint32_t)STAGE_BYTES);
            BULK_G2S(sa, Abase + (size_t)p * TILE_BYTES, TILE_BYTES, mb);
            BULK_G2S_MC(sb + rank * 16384,
                        Bbase + (size_t)p * TILE_BYTES + rank * 16384,
                        16384, mb, 0x3);
        }
    }

    for (int kt = 0; kt < NKT; kt++) {
        const int s = kt % 3;
        MBAR_WAIT(mb_full0 + s * 8, (kt / 3) & 1);

        if (warp == 0 && elect_one()) {
            uint32_t sa = sbase + SMEM_DATA + s * STAGE_BYTES;
            uint32_t sb = sa + TILE_BYTES;
            uint64_t bdesc = make_desc(sb);
#pragma unroll
            for (int d = 0; d < 2; d++) {
                uint64_t adesc = make_desc(sa + d * 128 * 128);
#pragma unroll
                for (int k4 = 0; k4 < 4; k4++) {
                    mma_f16_ss(tmem + d * 256, adesc + k4 * 2, bdesc + k4 * 2,
                               idesc, (kt > 0 || k4 > 0) ? 1u : 0u);
                }
            }
            asm volatile("tcgen05.commit.cta_group::1.mbarrier::arrive::one.shared::cluster.b64 [%0];"
                         :: "r"(mb_mma0 + (kt & 1) * 8) : "memory");
        }

        // mma(kt-1) done before refilling its stage ((kt+2)%3 == (kt-1)%3)
        if (kt >= 1) {
            int j = kt - 1;
            MBAR_WAIT(mb_mma0 + (j & 1) * 8, (j >> 1) & 1);
        }
        if (tid == 0 && kt + 2 < NKT) {
            int kn = kt + 2;
            int s2 = kn % 3;
            uint32_t mb = mb_full0 + s2 * 8;
            uint32_t sa = sbase + SMEM_DATA + s2 * STAGE_BYTES;
            uint32_t sb = sa + TILE_BYTES;
            MBAR_EXPECT_TX(mb, (uint32_t)STAGE_BYTES);
            BULK_G2S(sa, Abase + (size_t)kn * TILE_BYTES, TILE_BYTES, mb);
            BULK_G2S_MC(sb + rank * 16384,
                        Bbase + (size_t)kn * TILE_BYTES + rank * 16384,
                        16384, mb, 0x3);
        }
    }

    // Final commit: j=63 -> mma mbar[1], parity (63>>1)&1 = 1
    MBAR_WAIT(mb_mma0 + 8, 1);
    asm volatile("tcgen05.fence::after_thread_sync;" ::: "memory");

    // Epilogue: wg0 -> D0 rows m0..m0+127, wg1 -> D1 (+128). Bias fused.
    {
        const int wg = warp >> 2;
        const uint32_t dbase = tmem + wg * 256;
        const size_t row = (size_t)(m0 + wg * 128 + (warp & 3) * 32 + lane);
        float4* dst = (float4*)(out + row * E_DIM + n0);
        const float* bp = b2 + n0;
#pragma unroll
        for (int c0 = 0; c0 < BN; c0 += 32) {
            uint32_t r[32];
            TCGEN05_LD_X32(r, dbase + c0);
            asm volatile("tcgen05.wait::ld.sync.aligned;" ::: "memory");
#pragma unroll
            for (int q = 0; q < 8; q++) {
                float4 v;
                v.x = __uint_as_float(r[4 * q + 0]) + __ldg(bp + c0 + 4 * q + 0);
                v.y = __uint_as_float(r[4 * q + 1]) + __ldg(bp + c0 + 4 * q + 1);
                v.z = __uint_as_float(r[4 * q + 2]) + __ldg(bp + c0 + 4 * q + 2);
                v.w = __uint_as_float(r[4 * q + 3]) + __ldg(bp + c0 + 4 * q + 3);
                dst[(c0 >> 2) + q] = v;
            }
        }
        asm volatile("tcgen05.fence::before_thread_sync;" ::: "memory");
    }

    __syncthreads();
    if (tid == 0) {
        asm volatile("mbarrier.inval.shared.b64 [%0];" :: "r"(mb_full0)      : "memory");
        asm volatile("mbarrier.inval.shared.b64 [%0];" :: "r"(mb_full0 + 8)  : "memory");
        asm volatile("mbarrier.inval.shared.b64 [%0];" :: "r"(mb_full0 + 16) : "memory");
        asm volatile("mbarrier.inval.shared.b64 [%0];" :: "r"(mb_mma0)       : "memory");
        asm volatile("mbarrier.inval.shared.b64 [%0];" :: "r"(mb_mma0 + 8)   : "memory");
    }
    __syncthreads();
    if (warp == 0) {
        asm volatile("tcgen05.dealloc.cta_group::1.sync.aligned.b32 %0, %1;" :: "r"(tmem), "r"(512u));
    }
    asm volatile("barrier.cluster.arrive.aligned;" ::: "memory");
    asm volatile("barrier.cluster.wait.aligned;"   ::: "memory");
#endif  // HAS_BLACKWELL
}

// ===========================================================================
extern "C" void kernel_launch(void* const* d_in, const int* in_sizes, int n_in,
                              void* d_out, int out_size)
{
    const float* x     = (const float*)d_in[0];
    const float* theta = (const float*)d_in[1];
    const float* w1    = (const float*)d_in[2];
    const float* b1    = (const float*)d_in[3];
    const float* w2    = (const float*)d_in[4];
    const float* b2    = (const float*)d_in[5];
    float* out = (float*)d_out;

    dim3 gh(2, M_TOK / 64);
    compute_h_kernel<<<gh, 256>>>(x, theta, w1, b1);

    convert_w2_kernel<<<(E_DIM * F_DIM / 8) / 256, 256>>>(w2);

    cudaFuncSetAttribute(gemm_tc_kernel, cudaFuncAttributeMaxDynamicSharedMemorySize, GEMM_SMEM);
    dim3 gg(E_DIM / BN, M_TOK / BM);
    gemm_tc_kernel<<<gg, 256, GEMM_SMEM>>>(out, b2);
}

// round 7
// speedup vs baseline: 6.0211x; 1.1331x over previous
#include <cuda_runtime.h>
#include <cuda_fp16.h>
#include <cstdint>

// Shapes: x:[8,4096,1024]f32, theta:[8], w1:[4096,8], b1:[4096], w2:[1024,4096], b2:[1024]
// out:[8,4096,1024] f32
#define M_TOK 32768
#define E_DIM 1024
#define F_DIM 4096
#define NQ 8

#if defined(__CUDA_ARCH_FEAT_SM103_ALL) || defined(__CUDA_ARCH_FEAT_SM100_ALL) || !defined(__CUDA_ARCH__)
#define HAS_BLACKWELL 1
#else
#define HAS_BLACKWELL 0
#endif

// Tiled + SW64-swizzled layout: tile (blk256, kt) = 256 rows x 32 halves (64B rows) = 16KB
// at byte offset ((blk*128 + kt) << 14). Within tile, 16B chunk c (0..3) of row r:
//   soff = r*64 + ((c*16) ^ (((r>>1)&3)<<4))    [Swizzle<2,4,3> == SMEM_SWIZZLE_64B]
__device__ __half g_H[(size_t)M_TOK * F_DIM];     // 256 MiB
__device__ __half g_w2h[(size_t)E_DIM * F_DIM];   // 8 MiB

// ===========================================================================
// PTX helpers
// ===========================================================================
__device__ __forceinline__ uint32_t smem_u32(const void* p) {
    uint32_t a;
    asm("{ .reg .u64 t; cvta.to.shared.u64 t, %1; cvt.u32.u64 %0, t; }" : "=r"(a) : "l"(p));
    return a;
}

#define MBAR_INIT(addr, cnt) \
    asm volatile("mbarrier.init.shared.b64 [%0], %1;" :: "r"(addr), "r"(cnt) : "memory")

#define MBAR_WAIT(addr, parity) do { \
    uint32_t _mb = (addr); uint32_t _p = (parity); uint32_t _done; \
    asm volatile("{\n\t.reg .pred p;\n\t" \
        "mbarrier.try_wait.parity.acquire.cta.shared::cta.b64 p, [%1], %2;\n\t" \
        "selp.b32 %0, 1, 0, p;\n\t}" : "=r"(_done) : "r"(_mb), "r"(_p) : "memory"); \
    if (!_done) { \
        asm volatile("{\n\t.reg .pred P1;\n\t" \
            "WL_%=:\n\t" \
            "mbarrier.try_wait.parity.acquire.cta.shared::cta.b64 P1, [%0], %1, 0x989680;\n\t" \
            "@P1 bra.uni WD_%=;\n\t" \
            "bra.uni WL_%=;\n\t" \
            "WD_%=:\n\t}" :: "r"(_mb), "r"(_p) : "memory"); \
    } \
} while (0)

#define MBAR_EXPECT_TX(addr, bytes) \
    asm volatile("mbarrier.arrive.expect_tx.shared.b64 _, [%0], %1;" \
                 :: "r"(addr), "r"(bytes) : "memory")

#if HAS_BLACKWELL && defined(__CUDA_ARCH__)
__device__ __forceinline__ uint32_t elect_one() {
    uint32_t pred;
    asm volatile("{\n\t.reg .pred p;\n\telect.sync _|p, 0xFFFFFFFF;\n\tselp.b32 %0, 1, 0, p;\n\t}" : "=r"(pred));
    return pred;
}
__device__ __forceinline__ uint32_t ctarank() {
    uint32_t r;
    asm("mov.u32 %0, %%cluster_ctarank;" : "=r"(r));
    return r;
}

#define BULK_G2S(dst, src, bytes, mbar) \
    asm volatile("cp.async.bulk.shared::cluster.global.mbarrier::complete_tx::bytes [%0], [%1], %2, [%3];" \
        :: "r"(dst), "l"(src), "r"(bytes), "r"(mbar) : "memory")

#define BULK_G2S_MC(dst, src, bytes, mbar, mask) \
    asm volatile("cp.async.bulk.shared::cluster.global.mbarrier::complete_tx::bytes.multicast::cluster [%0], [%1], %2, [%3], %4;" \
        :: "r"(dst), "l"(src), "r"(bytes), "r"(mbar), "h"((unsigned short)(mask)) : "memory")

// MMA completion -> arrive free barrier in BOTH cluster CTAs
#define COMMIT_MC(mbar, mask) \
    asm volatile("tcgen05.commit.cta_group::1.mbarrier::arrive::one.shared::cluster.multicast::cluster.b64 [%0], %1;" \
        :: "r"(mbar), "h"((unsigned short)(mask)) : "memory")
#define COMMIT_LOCAL(mbar) \
    asm volatile("tcgen05.commit.cta_group::1.mbarrier::arrive::one.shared::cluster.b64 [%0];" \
        :: "r"(mbar) : "memory")

__device__ __forceinline__ void mma_f16_ss(uint32_t d_tmem, uint64_t a_desc, uint64_t b_desc,
                                           uint32_t idesc, uint32_t enable) {
    asm volatile(
        "{\n\t.reg .pred p;\n\t"
        "setp.ne.u32 p, %4, 0;\n\t"
        "tcgen05.mma.cta_group::1.kind::f16 [%0], %1, %2, %3, {%5, %5, %5, %5}, p;\n\t}"
        :: "r"(d_tmem), "l"(a_desc), "l"(b_desc), "r"(idesc), "r"(enable), "r"(0u)
        : "memory");
}

// Packed fp32x2 accumulating FMA (FFMA2): d = a*b + d
__device__ __forceinline__ void fma2(unsigned long long& d, unsigned long long a,
                                     unsigned long long b) {
    asm("fma.rn.f32x2 %0, %1, %2, %0;" : "+l"(d) : "l"(a), "l"(b));
}
__device__ __forceinline__ unsigned long long pack2(float lo, float hi) {
    unsigned long long o;
    asm("mov.b64 %0, {%1, %2};" : "=l"(o) : "f"(lo), "f"(hi));
    return o;
}
__device__ __forceinline__ void unpack2(float& lo, float& hi, unsigned long long v) {
    asm("mov.b64 {%0, %1}, %2;" : "=f"(lo), "=f"(hi) : "l"(v));
}
#endif

#define TCGEN05_LD_X32(r, addr) \
    asm volatile("tcgen05.ld.sync.aligned.32x32b.x32.b32 " \
        "{%0, %1, %2, %3, %4, %5, %6, %7, " \
        " %8, %9, %10, %11, %12, %13, %14, %15, " \
        " %16, %17, %18, %19, %20, %21, %22, %23, " \
        " %24, %25, %26, %27, %28, %29, %30, %31}, [%32];" \
        : "=r"((r)[0]),  "=r"((r)[1]),  "=r"((r)[2]),  "=r"((r)[3]), \
          "=r"((r)[4]),  "=r"((r)[5]),  "=r"((r)[6]),  "=r"((r)[7]), \
          "=r"((r)[8]),  "=r"((r)[9]),  "=r"((r)[10]), "=r"((r)[11]), \
          "=r"((r)[12]), "=r"((r)[13]), "=r"((r)[14]), "=r"((r)[15]), \
          "=r"((r)[16]), "=r"((r)[17]), "=r"((r)[18]), "=r"((r)[19]), \
          "=r"((r)[20]), "=r"((r)[21]), "=r"((r)[22]), "=r"((r)[23]), \
          "=r"((r)[24]), "=r"((r)[25]), "=r"((r)[26]), "=r"((r)[27]), \
          "=r"((r)[28]), "=r"((r)[29]), "=r"((r)[30]), "=r"((r)[31]) \
        : "r"(addr))

// SW64 K-major smem descriptor: layout=4, version=1 (Blackwell), SBO=32 (512B = 8 rows x 64B), LBO=1
static constexpr uint64_t DESC_BASE_SW64 =
    (uint64_t(4) << 61) | (uint64_t(1) << 46) | (uint64_t(32) << 32) | (uint64_t(1) << 16);
__device__ __forceinline__ uint64_t make_desc64(uint32_t addr) {
    return DESC_BASE_SW64 | (uint64_t)((addr >> 4) & 0x3FFF);
}

// ===========================================================================
// Kernel 1: H (tiled+SW64 fp16) = relu(q @ w1^T + b1), q = cos(x[:, :8])*cos(theta)
// Grid (4, 512). Thread owns 4 consecutive f (one 8B half-chunk), loops 64 tokens.
// ===========================================================================
__global__ __launch_bounds__(256) void compute_h_kernel(
    const float* __restrict__ x, const float* __restrict__ theta,
    const float* __restrict__ w1, const float* __restrict__ b1)
{
    __shared__ float sq[64 * NQ];   // cos(x); cos(theta) folded into weights
    const int tid = threadIdx.x;
    const int hch = blockIdx.x * 256 + tid;    // 0..1023 half-chunks
    const int kt  = hch >> 3;                  // K-tile 0..127
    const int q   = hch & 7;                   // 4-wide group in tile (8 per tile)
    const int c16 = q >> 1;                    // 16B chunk 0..3
    const int hh  = q & 1;                     // 8B half within chunk
    const int f0  = kt * 32 + q * 4;
    const int ty0 = blockIdx.y * 64;

    for (int idx = tid; idx < 64 * NQ; idx += 256) {
        int t = idx >> 3, i = idx & 7;
        sq[idx] = cosf(x[(size_t)(ty0 + t) * E_DIM + i]);
    }

    float ct[NQ];
#pragma unroll
    for (int i = 0; i < NQ; i++) ct[i] = cosf(theta[i]);

#if HAS_BLACKWELL && defined(__CUDA_ARCH__)
    // wp[i][j] = ( w1[f0+2j][i]*ct[i], w1[f0+2j+1][i]*ct[i] ),  j = 0..1
    unsigned long long wp[NQ][2];
#pragma unroll
    for (int j = 0; j < 2; j++) {
        const float* r0 = w1 + (size_t)(f0 + 2 * j) * NQ;
        const float* r1 = r0 + NQ;
        float4 a0 = *(const float4*)(r0);
        float4 a1 = *(const float4*)(r0 + 4);
        float4 c0 = *(const float4*)(r1);
        float4 c1 = *(const float4*)(r1 + 4);
        wp[0][j] = pack2(a0.x * ct[0], c0.x * ct[0]);
        wp[1][j] = pack2(a0.y * ct[1], c0.y * ct[1]);
        wp[2][j] = pack2(a0.z * ct[2], c0.z * ct[2]);
        wp[3][j] = pack2(a0.w * ct[3], c0.w * ct[3]);
        wp[4][j] = pack2(a1.x * ct[4], c1.x * ct[4]);
        wp[5][j] = pack2(a1.y * ct[5], c1.y * ct[5]);
        wp[6][j] = pack2(a1.z * ct[6], c1.z * ct[6]);
        wp[7][j] = pack2(a1.w * ct[7], c1.w * ct[7]);
    }
    unsigned long long bb[2];
#pragma unroll
    for (int j = 0; j < 2; j++) bb[j] = pack2(b1[f0 + 2 * j], b1[f0 + 2 * j + 1]);

    __syncthreads();

    for (int n = 0; n < 64; n++) {
        unsigned long long acc[2] = { bb[0], bb[1] };
#pragma unroll
        for (int i = 0; i < NQ; i++) {
            float qv = sq[n * NQ + i];
            unsigned long long q2 = pack2(qv, qv);
#pragma unroll
            for (int j = 0; j < 2; j++) fma2(acc[j], q2, wp[i][j]);
        }
        uint2 vals;
        uint32_t* vp = (uint32_t*)&vals;
#pragma unroll
        for (int j = 0; j < 2; j++) {
            float lo, hi;
            unpack2(lo, hi, acc[j]);
            __half2 h2 = __floats2half2_rn(fmaxf(lo, 0.f), fmaxf(hi, 0.f));
            vp[j] = *(uint32_t*)&h2;
        }
        size_t t = (size_t)(ty0 + n);
        size_t mb = t >> 8;
        uint32_t r = (uint32_t)(t & 255);
        size_t off = ((mb * 128 + kt) << 14) + (size_t)r * 64
                   + (uint32_t)(((c16 * 16) ^ (((r >> 1) & 3) << 4)) + hh * 8);
        *(uint2*)((char*)g_H + off) = vals;
    }
#else
    // Scalar fallback (generic-PTX target only; never selected on GB300)
    float w[4][NQ], bbs[4];
#pragma unroll
    for (int fp = 0; fp < 4; fp++) {
#pragma unroll
        for (int i = 0; i < NQ; i++) w[fp][i] = w1[(size_t)(f0 + fp) * NQ + i] * ct[i];
        bbs[fp] = b1[f0 + fp];
    }
    __syncthreads();
    for (int n = 0; n < 64; n++) {
        __half hv[4];
#pragma unroll
        for (int fp = 0; fp < 4; fp++) {
            float acc = bbs[fp];
#pragma unroll
            for (int i = 0; i < NQ; i++) acc = fmaf(sq[n * NQ + i], w[fp][i], acc);
            hv[fp] = __float2half(fmaxf(acc, 0.f));
        }
        size_t t = (size_t)(ty0 + n);
        size_t mb = t >> 8;
        uint32_t r = (uint32_t)(t & 255);
        size_t off = ((mb * 128 + kt) << 14) + (size_t)r * 64
                   + (uint32_t)(((c16 * 16) ^ (((r >> 1) & 3) << 4)) + hh * 8);
        *(uint2*)((char*)g_H + off) = *(uint2*)hv;
    }
#endif
}

// ===========================================================================
// Kernel 2: w2 f32 -> f16 in tiled+SW64 layout
// idx -> c=idx&3, r=(idx>>2)&255, kt=(idx>>10)&127, nb=idx>>17
// ===========================================================================
__global__ __launch_bounds__(256) void convert_w2_kernel(const float* __restrict__ w2)
{
    int idx = blockIdx.x * 256 + threadIdx.x;      // over E*F/8 = 524288 16B chunks
    int c  = idx & 3;
    int r  = (idx >> 2) & 255;
    int kt = (idx >> 10) & 127;
    int nb = idx >> 17;

    const float* src = w2 + ((size_t)(nb * 256 + r)) * F_DIM + kt * 32 + c * 8;
    float4 v0 = *(const float4*)(src);
    float4 v1 = *(const float4*)(src + 4);
    __half2 h0 = __floats2half2_rn(v0.x, v0.y);
    __half2 h1 = __floats2half2_rn(v0.z, v0.w);
    __half2 h2 = __floats2half2_rn(v1.x, v1.y);
    __half2 h3 = __floats2half2_rn(v1.z, v1.w);
    uint4 out;
    out.x = *(uint32_t*)&h0; out.y = *(uint32_t*)&h1;
    out.z = *(uint32_t*)&h2; out.w = *(uint32_t*)&h3;

    size_t off = (((size_t)nb * 128 + kt) << 14) + (size_t)r * 64
               + (uint32_t)((c * 16) ^ (((r >> 1) & 3) << 4));
    *(uint4*)((char*)g_w2h + off) = out;
}

// ===========================================================================
// Kernel 3: tcgen05 GEMM, BM=256, BN=256, KC=32 halves (64B SW64 rows);
// 6-stage ring, warp-specialized: tid0 = producer (bulk loads, A plain +
// B half multicast across (1,2,1) cluster), warp1-elect = MMA issuer.
// free[s] barriers armed by MULTICAST commit (both CTAs) -> safe B-buffer reuse.
// ===========================================================================
#define BM 256
#define BN 256
#define KC 32
#define NKT (F_DIM / KC)              // 128
#define TILE_B 16384
#define STAGE_BYTES (2 * TILE_B)      // A + B = 32KB
#define NSTAGE 6
#define SMEM_DATA 1024
#define GEMM_SMEM (SMEM_DATA + NSTAGE * STAGE_BYTES)   // 197632

__global__ __launch_bounds__(256, 1) __cluster_dims__(1, 2, 1)
void gemm_tc_kernel(float* __restrict__ out, const float* __restrict__ b2)
{
#if HAS_BLACKWELL && defined(__CUDA_ARCH__)
    extern __shared__ char smem[];
    const uint32_t sbase = smem_u32(smem);
    const int tid  = threadIdx.x;
    const int warp = tid >> 5;
    const int lane = tid & 31;
    const int nb = blockIdx.x;
    const int n0 = nb * BN;
    const int m0 = blockIdx.y * BM;
    const uint32_t rank = ctarank();   // 0/1 within the y-pair

    // mbar layout: full[6] at +8..+48, free[6] at +64..+104, done at +120
    const uint32_t mb_full0 = sbase + 8;
    const uint32_t mb_free0 = sbase + 64;
    const uint32_t mb_done  = sbase + 120;

    if (warp == 0) {
        asm volatile("tcgen05.alloc.cta_group::1.sync.aligned.shared::cta.b32 [%0], %1;"
                     :: "r"(sbase), "r"(512u) : "memory");
    }
    __syncthreads();
    uint32_t tmem;
    asm volatile("ld.shared.b32 %0, [%1];" : "=r"(tmem) : "r"(sbase));
    if (warp == 0)
        asm volatile("tcgen05.relinquish_alloc_permit.cta_group::1.sync.aligned;");

    if (tid == 0) {
#pragma unroll
        for (int s = 0; s < NSTAGE; s++) {
            MBAR_INIT(mb_full0 + s * 8, 1);
            MBAR_INIT(mb_free0 + s * 8, 2);   // 2 = multicast commit from each CTA
        }
        MBAR_INIT(mb_done, 1);
    }
    __syncthreads();
    // All cluster mbarriers live before any multicast targets them.
    asm volatile("barrier.cluster.arrive.aligned;" ::: "memory");
    asm volatile("barrier.cluster.wait.aligned;"   ::: "memory");

    const char* Abase = (const char*)g_H   + ((size_t)blockIdx.y * 128) * TILE_B;
    const char* Bbase = (const char*)g_w2h + ((size_t)nb * 128) * TILE_B;
    const uint32_t idesc = (1u << 4) | ((BN / 8) << 17) | ((128 / 16) << 24);

    if (tid == 0) {
        // ---- producer ----
        for (int kn = 0; kn < NKT; kn++) {
            const int s = kn % NSTAGE;
            const int r = kn / NSTAGE;
            if (r >= 1) MBAR_WAIT(mb_free0 + s * 8, (r - 1) & 1);
            const uint32_t mb = mb_full0 + s * 8;
            const uint32_t sa = sbase + SMEM_DATA + s * STAGE_BYTES;
            const uint32_t sb = sa + TILE_B;
            MBAR_EXPECT_TX(mb, (uint32_t)STAGE_BYTES);   // A 16K + own B 8K + peer B 8K
            BULK_G2S(sa, Abase + (size_t)kn * TILE_B, TILE_B, mb);
            BULK_G2S_MC(sb + rank * 8192,
                        Bbase + (size_t)kn * TILE_B + rank * 8192,
                        8192, mb, 0x3);
        }
    } else if (warp == 1) {
        // ---- MMA issuer ----
        if (elect_one()) {
            for (int kt = 0; kt < NKT; kt++) {
                const int s = kt % NSTAGE;
                const int r = kt / NSTAGE;
                MBAR_WAIT(mb_full0 + s * 8, r & 1);
                const uint32_t sa = sbase + SMEM_DATA + s * STAGE_BYTES;
                const uint64_t bdesc = make_desc64(sa + TILE_B);
#pragma unroll
                for (int d = 0; d < 2; d++) {
                    uint64_t adesc = make_desc64(sa + d * 8192);
#pragma unroll
                    for (int k2 = 0; k2 < 2; k2++) {
                        mma_f16_ss(tmem + d * 256, adesc + k2 * 2, bdesc + k2 * 2,
                                   idesc, (kt > 0 || k2 > 0) ? 1u : 0u);
                    }
                }
                COMMIT_MC(mb_free0 + s * 8, 0x3);
            }
            COMMIT_LOCAL(mb_done);   // arrives when ALL prior MMAs complete
        }
    }

    // ---- everyone: wait for all MMA work ----
    MBAR_WAIT(mb_done, 0);
    asm volatile("tcgen05.fence::after_thread_sync;" ::: "memory");

    // Epilogue: wg0 reads D0 (rows m0..m0+127), wg1 reads D1 (+128). Bias fused.
    {
        const int wg = warp >> 2;
        const uint32_t dbase = tmem + wg * 256;
        const size_t row = (size_t)(m0 + wg * 128 + (warp & 3) * 32 + lane);
        float4* dst = (float4*)(out + row * E_DIM + n0);
        const float* bp = b2 + n0;
#pragma unroll
        for (int c0 = 0; c0 < BN; c0 += 32) {
            uint32_t r[32];
            TCGEN05_LD_X32(r, dbase + c0);
            asm volatile("tcgen05.wait::ld.sync.aligned;" ::: "memory");
#pragma unroll
            for (int q = 0; q < 8; q++) {
                float4 v;
                v.x = __uint_as_float(r[4 * q + 0]) + __ldg(bp + c0 + 4 * q + 0);
                v.y = __uint_as_float(r[4 * q + 1]) + __ldg(bp + c0 + 4 * q + 1);
                v.z = __uint_as_float(r[4 * q + 2]) + __ldg(bp + c0 + 4 * q + 2);
                v.w = __uint_as_float(r[4 * q + 3]) + __ldg(bp + c0 + 4 * q + 3);
                dst[(c0 >> 2) + q] = v;
            }
        }
        asm volatile("tcgen05.fence::before_thread_sync;" ::: "memory");
    }

    __syncthreads();
    if (tid == 0) {
#pragma unroll
        for (int s = 0; s < NSTAGE; s++) {
            asm volatile("mbarrier.inval.shared.b64 [%0];" :: "r"(mb_full0 + s * 8) : "memory");
            asm volatile("mbarrier.inval.shared.b64 [%0];" :: "r"(mb_free0 + s * 8) : "memory");
        }
        asm volatile("mbarrier.inval.shared.b64 [%0];" :: "r"(mb_done) : "memory");
    }
    __syncthreads();
    if (warp == 0) {
        asm volatile("tcgen05.dealloc.cta_group::1.sync.aligned.b32 %0, %1;" :: "r"(tmem), "r"(512u));
    }
    asm volatile("barrier.cluster.arrive.aligned;" ::: "memory");
    asm volatile("barrier.cluster.wait.aligned;"   ::: "memory");
#endif  // HAS_BLACKWELL
}

// ===========================================================================
extern "C" void kernel_launch(void* const* d_in, const int* in_sizes, int n_in,
                              void* d_out, int out_size)
{
    const float* x     = (const float*)d_in[0];
    const float* theta = (const float*)d_in[1];
    const float* w1    = (const float*)d_in[2];
    const float* b1    = (const float*)d_in[3];
    const float* w2    = (const float*)d_in[4];
    const float* b2    = (const float*)d_in[5];
    float* out = (float*)d_out;

    dim3 gh(4, M_TOK / 64);
    compute_h_kernel<<<gh, 256>>>(x, theta, w1, b1);

    convert_w2_kernel<<<(E_DIM * F_DIM / 8) / 256, 256>>>(w2);

    cudaFuncSetAttribute(gemm_tc_kernel, cudaFuncAttributeMaxDynamicSharedMemorySize, GEMM_SMEM);
    dim3 gg(E_DIM / BN, M_TOK / BM);
    gemm_tc_kernel<<<gg, 256, GEMM_SMEM>>>(out, b2);
}